// round 9
// baseline (speedup 1.0000x reference)
#include <cuda_runtime.h>
#include <cuda_bf16.h>
#include <math.h>

#define NN   768
#define KK   32
#define CS   384
#define CZ   128
#define CG   16
#define NH   4
#define EE   (NN*KK)
#define NRBF 64

typedef unsigned long long ull;
typedef unsigned int uint;

// ---- f32x2 packed helpers (sm_100+) ----
__device__ __forceinline__ ull pk2(float lo, float hi) {
    ull r; asm("mov.b64 %0, {%1,%2};" : "=l"(r) : "f"(lo), "f"(hi)); return r;
}
__device__ __forceinline__ void upk2(ull v, float& lo, float& hi) {
    asm("mov.b64 {%0,%1}, %2;" : "=f"(lo), "=f"(hi) : "l"(v));
}
__device__ __forceinline__ ull ffma2(ull a, ull b, ull c) {
    ull d; asm("fma.rn.f32x2 %0, %1, %2, %3;" : "=l"(d) : "l"(a), "l"(b), "l"(c)); return d;
}
__device__ __forceinline__ float tanh_fast(float x) {
    float y; asm("tanh.approx.f32 %0, %1;" : "=f"(y) : "f"(x)); return y;
}
__device__ __forceinline__ __nv_bfloat162 u2b(uint u) {
    return *reinterpret_cast<__nv_bfloat162*>(&u);
}
// ---- tf32 helpers ----
__device__ __forceinline__ uint f2tf32(float x) {
    uint u; asm("cvt.rna.tf32.f32 %0, %1;" : "=r"(u) : "f"(x)); return u;
}
__device__ __forceinline__ void mma_tf32(float& d0, float& d1, float& d2, float& d3,
                                         uint a0, uint a1, uint a2, uint a3,
                                         uint b0, uint b1) {
    asm("mma.sync.aligned.m16n8k8.row.col.f32.tf32.tf32.f32 "
        "{%0,%1,%2,%3}, {%4,%5,%6,%7}, {%8,%9}, {%0,%1,%2,%3};"
        : "+f"(d0), "+f"(d1), "+f"(d2), "+f"(d3)
        : "r"(a0), "r"(a1), "r"(a2), "r"(a3), "r"(b0), "r"(b1));
}

// ---------------- scratch (device globals; allocation-free) ----------------
__device__ float g_nl[NN*CG];
__device__ float g_nr[NN*CG];
__device__ float g_z[(size_t)EE*CZ];
__device__ float g_qkvo[(size_t)EE*512];        // q[0:128) k[128:256) v[256:384) sig(og)[384:512)
__device__ float g_bias[(size_t)NN*NH*KK*KK];   // [n][h][i][j]
__device__ float g_og[(size_t)EE*CZ];
__device__ float g_wcat[CZ*512];
__device__ float g_bcat[512];

// ---------------- kernel: concat projection weights ----------------
__global__ void k_concat(const float* __restrict__ wq, const float* __restrict__ bq,
                         const float* __restrict__ wkv, const float* __restrict__ bkv,
                         const float* __restrict__ wog, const float* __restrict__ bog)
{
    int c = blockIdx.x;
    int t = threadIdx.x;
    float v;
    if (t < 128)       v = wq[c*128 + t];
    else if (t < 384)  v = wkv[c*256 + (t-128)];
    else               v = wog[c*128 + (t-384)];
    g_wcat[c*512 + t] = v;
    if (c == 0) {
        float b;
        if (t < 128)      b = bq[t];
        else if (t < 384) b = bkv[t-128];
        else              b = bog[t-384];
        g_bcat[t] = b;
    }
}

// ---------------- kernel: node left/right projections ----------------
__global__ void k_nlr(const float* __restrict__ nf,
                      const float* __restrict__ wl, const float* __restrict__ bl,
                      const float* __restrict__ wr, const float* __restrict__ br)
{
    int n = blockIdx.x;
    int t = threadIdx.x;          // 32 threads
    int c0 = t & 15;
    const float* w = (t < 16) ? wl : wr;
    float acc = (t < 16) ? bl[c0] : br[c0];
    const float* row = nf + (size_t)n*CS;
    #pragma unroll 4
    for (int c = 0; c < CS; c++) acc += __ldg(row + c) * __ldg(w + c*CG + c0);
    if (t < 16) g_nl[n*CG + c0] = acc;
    else        g_nr[n*CG + c0] = acc;
}

// ---------------- kernel: LayerNorm over c_z ----------------
__global__ __launch_bounds__(128) void k_ln(const float* __restrict__ ef,
                                            const float* __restrict__ gam,
                                            const float* __restrict__ bet)
{
    int e = blockIdx.x;
    int t = threadIdx.x;
    float x = ef[(size_t)e*CZ + t];
    float s = x, s2 = x*x;
    #pragma unroll
    for (int o = 16; o > 0; o >>= 1) {
        s  += __shfl_xor_sync(0xffffffffu, s,  o);
        s2 += __shfl_xor_sync(0xffffffffu, s2, o);
    }
    __shared__ float ws[4], ws2[4];
    int w = t >> 5;
    if ((t & 31) == 0) { ws[w] = s; ws2[w] = s2; }
    __syncthreads();
    s  = ws[0]  + ws[1]  + ws[2]  + ws[3];
    s2 = ws2[0] + ws2[1] + ws2[2] + ws2[3];
    float mu  = s  * (1.f/128.f);
    float var = s2 * (1.f/128.f) - mu*mu;
    float inv = rsqrtf(var + 1e-5f);
    g_z[(size_t)e*CZ + t] = (x - mu) * inv * gam[t] + bet[t];
}

// ---------------- kernel: tf32 tensor-core GEMM ----------------
__global__ __launch_bounds__(256) void k_gemm_tc(const float* __restrict__ A,
                                                 const float* __restrict__ B,
                                                 float* __restrict__ C,
                                                 int ldb,
                                                 const float* __restrict__ bias,
                                                 int sigStart)
{
    __shared__ uint As[32*132];   // [k][m] tf32 bits
    __shared__ uint Bs[32*132];   // [k][n] tf32 bits
    int tid = threadIdx.x;
    int row0 = blockIdx.x * 128;
    int n0   = blockIdx.y * 128;
    int wid  = tid >> 5;
    int lane = tid & 31;
    int warp_m = wid >> 2;          // 0..1
    int warp_n = wid & 3;           // 0..3
    int gid = lane >> 2;            // 0..7
    int tig = lane & 3;             // 0..3
    int m0w = warp_m * 64;
    int n0w = warp_n * 32;

    float acc[4][4][4];
    #pragma unroll
    for (int mt = 0; mt < 4; mt++)
        #pragma unroll
        for (int nt = 0; nt < 4; nt++)
            #pragma unroll
            for (int q = 0; q < 4; q++) acc[mt][nt][q] = 0.f;

    for (int k0 = 0; k0 < 128; k0 += 32) {
        #pragma unroll
        for (int it = 0; it < 4; it++) {
            int idx = tid + it*256;
            int r = idx >> 3, kc = idx & 7;
            float4 v = *(const float4*)(A + (size_t)(row0 + r)*128 + k0 + kc*4);
            As[(kc*4+0)*132 + r] = f2tf32(v.x);
            As[(kc*4+1)*132 + r] = f2tf32(v.y);
            As[(kc*4+2)*132 + r] = f2tf32(v.z);
            As[(kc*4+3)*132 + r] = f2tf32(v.w);
        }
        #pragma unroll
        for (int it = 0; it < 4; it++) {
            int idx = tid + it*256;
            int r = idx >> 5, nc = idx & 31;
            float4 v = *(const float4*)(B + (size_t)(k0 + r)*ldb + n0 + nc*4);
            Bs[r*132 + nc*4 + 0] = f2tf32(v.x);
            Bs[r*132 + nc*4 + 1] = f2tf32(v.y);
            Bs[r*132 + nc*4 + 2] = f2tf32(v.z);
            Bs[r*132 + nc*4 + 3] = f2tf32(v.w);
        }
        __syncthreads();
        #pragma unroll
        for (int ks = 0; ks < 4; ks++) {
            int kb = ks * 8;
            const uint* a_lo = As + (kb + tig    )*132;
            const uint* a_hi = As + (kb + tig + 4)*132;
            uint af[4][4];
            #pragma unroll
            for (int mt = 0; mt < 4; mt++) {
                int ra = m0w + mt*16 + gid;
                af[mt][0] = a_lo[ra];
                af[mt][1] = a_lo[ra + 8];
                af[mt][2] = a_hi[ra];
                af[mt][3] = a_hi[ra + 8];
            }
            const uint* b_lo = Bs + (kb + tig    )*132;
            const uint* b_hi = Bs + (kb + tig + 4)*132;
            uint bf[4][2];
            #pragma unroll
            for (int nt = 0; nt < 4; nt++) {
                int cb = n0w + nt*8 + gid;
                bf[nt][0] = b_lo[cb];
                bf[nt][1] = b_hi[cb];
            }
            #pragma unroll
            for (int mt = 0; mt < 4; mt++)
                #pragma unroll
                for (int nt = 0; nt < 4; nt++)
                    mma_tf32(acc[mt][nt][0], acc[mt][nt][1], acc[mt][nt][2], acc[mt][nt][3],
                             af[mt][0], af[mt][1], af[mt][2], af[mt][3],
                             bf[nt][0], bf[nt][1]);
        }
        __syncthreads();
    }
    #pragma unroll
    for (int mt = 0; mt < 4; mt++) {
        int rowa = row0 + m0w + mt*16 + gid;
        #pragma unroll
        for (int nt = 0; nt < 4; nt++) {
            int col = n0 + n0w + nt*8 + 2*tig;
            float b0 = __ldg(bias + col), b1 = __ldg(bias + col + 1);
            float v0 = acc[mt][nt][0] + b0;
            float v1 = acc[mt][nt][1] + b1;
            float v2 = acc[mt][nt][2] + b0;
            float v3 = acc[mt][nt][3] + b1;
            if (col   >= sigStart) { v0 = __fdividef(1.f, 1.f + __expf(-v0));
                                     v2 = __fdividef(1.f, 1.f + __expf(-v2)); }
            if (col+1 >= sigStart) { v1 = __fdividef(1.f, 1.f + __expf(-v1));
                                     v3 = __fdividef(1.f, 1.f + __expf(-v3)); }
            float2 s0 = {v0, v1};
            float2 s1 = {v2, v3};
            *(float2*)(C + (size_t)rowa*ldb + col)     = s0;
            *(float2*)(C + (size_t)(rowa+8)*ldb + col) = s1;
        }
    }
}

// ---------------- kernel: triangle bias ----------------
// 1024 threads: each thread owns ONE (i,j) pair -> half the per-thread state
// of the 512-thread version, so the full block fits the RF at 64 regs and the
// SM runs 32 warps (occ 50%) instead of 16 (24.9%). Latency-bound -> hidden.
// gate[i,j,c] = sum_k e1[i,k] * M[c,j,k],  M[c,j,k] = sum_l e2[j,l] W[k*16+l,c].
__global__ __launch_bounds__(1024, 1) void k_tri(const int* __restrict__ ei,
                                                 const float* __restrict__ trans,
                                                 const float* __restrict__ W,       // [256,128]
                                                 const float* __restrict__ b_bgate,
                                                 const float* __restrict__ wdist,   // [64,128]
                                                 const float* __restrict__ b_dist,
                                                 const float* __restrict__ wtob)    // [128,4]
{
    __shared__ float          s_e2t[16*32];     // [l][j]                   2048B
    __shared__ float          s_t[32*4];        //                           512B
    __shared__ ull            s_wt2[128*2];     // [c][h-pair]              2048B
    __shared__ __nv_bfloat16  s_wdc[16*72];     // [c in chunk][r] bf16     2304B
    __shared__ __nv_bfloat16  s_M[16*32*40];    // [c][j][k] bf16, str 40  40960B
    __shared__ ull            s_bgd[128];       // pk2(bg, bd)              1024B
    __shared__ int            s_src[32];        //                           128B

    int n = blockIdx.x;
    int tid = threadIdx.x;

    if (tid < 32) s_src[tid] = ei[n*KK + tid];
    __syncthreads();
    if (tid < 512) {
        int i = tid >> 4, k = tid & 15;
        s_e2t[k*32 + i] = g_nr[s_src[i]*CG + k];
    } else {
        int t2 = tid - 512;
        if (t2 < 256) {
            int c = t2 >> 1, p = t2 & 1;
            s_wt2[c*2 + p] = pk2(wtob[c*4 + 2*p], wtob[c*4 + 2*p + 1]);
        } else if (t2 < 384) {
            s_bgd[t2 - 256] = pk2(b_bgate[t2 - 256], b_dist[t2 - 256]);
        } else if (t2 < 480) {
            int q = t2 - 384;
            int i = q/3, c = q - i*3;
            s_t[i*4+c] = trans[s_src[i]*3 + c];
        }
    }
    __syncthreads();

    // ---- per-thread (i,j) assignment (phase B) ----
    int j = tid >> 5;               // 0..31 (warp-uniform)
    int i = tid & 31;               // lane

    int r0;
    __nv_bfloat162 rbfh[8];         // 16 taps, pair-packed bf16
    __nv_bfloat162 e1h[8];          // e1[i,:] pair-packed bf16
    {
        float dx = s_t[i*4+0] - s_t[j*4+0] + 1e-8f;
        float dy = s_t[i*4+1] - s_t[j*4+1] + 1e-8f;
        float dz = s_t[i*4+2] - s_t[j*4+2] + 1e-8f;
        float dd = sqrtf(dx*dx + dy*dy + dz*dz);
        int f = (int)(dd * (63.0f/20.0f));
        int rr0 = (f - 4) & ~7;          // 16B(bf16)-aligned 16-tap window
        rr0 = max(rr0, 0); rr0 = min(rr0, 48);
        r0 = rr0;
        #pragma unroll
        for (int r2 = 0; r2 < 8; r2++) {
            float mu0 = (float)(rr0 + 2*r2)     * (20.0f/63.0f);
            float mu1 = (float)(rr0 + 2*r2 + 1) * (20.0f/63.0f);
            float x0 = (dd - mu0) * 3.2f;
            float x1 = (dd - mu1) * 3.2f;
            rbfh[r2] = __floats2bfloat162_rn(__expf(-x0*x0), __expf(-x1*x1));
        }
        const float4* ep = (const float4*)(g_nl + s_src[i]*CG);
        #pragma unroll
        for (int q = 0; q < 4; q++) {
            float4 e4 = __ldg(ep + q);
            e1h[2*q  ] = __floats2bfloat162_rn(e4.x, e4.y);
            e1h[2*q+1] = __floats2bfloat162_rn(e4.z, e4.w);
        }
    }

    // ---- phase A assignment: 1024 threads = 32 j x 16 k x 2 channel-halves
    int jA = tid & 31;
    int kA = (tid >> 5) & 15;
    int hf = tid >> 9;              // 0..1

    ull bacc[2] = {0ull, 0ull};     // [h-pair], f32x2 over (h0,h1),(h2,h3)

    for (int ch = 0; ch < 8; ch++) {
        int cb = ch * 16;
        // stage wdist chunk as bf16: 1024 threads cover 16c x 64r
        {
            int c = tid & 15, r = tid >> 4;      // r 0..63
            s_wdc[c*72 + r] = __float2bfloat16_rn(__ldg(wdist + r*128 + cb + c));
        }
        // phase A: each thread 8 channels (cb + hf*8 .. +7)
        {
            ull a2[4] = {0ull, 0ull, 0ull, 0ull};
            const float* Wbase = W + cb + hf*8;
            #pragma unroll
            for (int l = 0; l < 16; l++) {
                float e2v = s_e2t[l*32 + jA];
                ull e2p = pk2(e2v, e2v);
                const ulonglong2* Wp = (const ulonglong2*)(Wbase + (size_t)(kA*16 + l)*128);
                ulonglong2 w01 = __ldg(Wp), w23 = __ldg(Wp+1);
                a2[0] = ffma2(e2p, w01.x, a2[0]); a2[1] = ffma2(e2p, w01.y, a2[1]);
                a2[2] = ffma2(e2p, w23.x, a2[2]); a2[3] = ffma2(e2p, w23.y, a2[3]);
            }
            #pragma unroll
            for (int c2 = 0; c2 < 4; c2++) {
                float lo, hi;
                upk2(a2[c2], lo, hi);
                int cloc = hf*8 + 2*c2;
                s_M[((cloc  )*32 + jA)*40 + kA] = __float2bfloat16_rn(lo);
                s_M[((cloc+1)*32 + jA)*40 + kA] = __float2bfloat16_rn(hi);
            }
        }
        __syncthreads();
        // phase B: one (i,j) per thread, 16 channels
        #pragma unroll 1
        for (int cc = 0; cc < 16; cc++) {
            int c = cb + cc;
            const __nv_bfloat16* mrow = s_M + (cc*32 + j)*40;   // j warp-uniform -> broadcast
            uint4 ma = *(const uint4*)(mrow);
            uint4 mb = *(const uint4*)(mrow + 8);
            float bg, bd;
            upk2(s_bgd[c], bg, bd);
            __nv_bfloat162 ga = __floats2bfloat162_rn(0.f, 0.f);
            ga = __hfma2(e1h[0], u2b(ma.x), ga);
            ga = __hfma2(e1h[1], u2b(ma.y), ga);
            ga = __hfma2(e1h[2], u2b(ma.z), ga);
            ga = __hfma2(e1h[3], u2b(ma.w), ga);
            ga = __hfma2(e1h[4], u2b(mb.x), ga);
            ga = __hfma2(e1h[5], u2b(mb.y), ga);
            ga = __hfma2(e1h[6], u2b(mb.z), ga);
            ga = __hfma2(e1h[7], u2b(mb.w), ga);
            float g = __low2float(ga) + __high2float(ga) + bg;
            float sg = 0.5f + 0.5f*tanh_fast(0.5f*g);
            const __nv_bfloat16* wrow = s_wdc + cc*72 + r0;
            uint4 wa = *(const uint4*)(wrow);
            uint4 wb = *(const uint4*)(wrow + 8);
            __nv_bfloat162 da_ = __floats2bfloat162_rn(0.f, 0.f);
            da_ = __hfma2(rbfh[0], u2b(wa.x), da_);
            da_ = __hfma2(rbfh[1], u2b(wa.y), da_);
            da_ = __hfma2(rbfh[2], u2b(wa.z), da_);
            da_ = __hfma2(rbfh[3], u2b(wa.w), da_);
            da_ = __hfma2(rbfh[4], u2b(wb.x), da_);
            da_ = __hfma2(rbfh[5], u2b(wb.y), da_);
            da_ = __hfma2(rbfh[6], u2b(wb.z), da_);
            da_ = __hfma2(rbfh[7], u2b(wb.w), da_);
            float db = __low2float(da_) + __high2float(da_) + bd;
            float t = sg * db;
            ull tp = pk2(t, t);
            const ull* wt = s_wt2 + c*2;
            bacc[0] = ffma2(tp, wt[0], bacc[0]);
            bacc[1] = ffma2(tp, wt[1], bacc[1]);
        }
        __syncthreads();
    }
    {
        float b0, b1, b2, b3;
        upk2(bacc[0], b0, b1);
        upk2(bacc[1], b2, b3);
        size_t base = ((size_t)n*NH)*KK*KK + (size_t)i*KK + j;
        g_bias[base            ] = b0;
        g_bias[base + KK*KK    ] = b1;
        g_bias[base + 2*KK*KK  ] = b2;
        g_bias[base + 3*KK*KK  ] = b3;
    }
}

// ---------------- kernel: attention over K neighbors, per node ----------------
__global__ __launch_bounds__(128) void k_attn()
{
    int n = blockIdx.x;
    int tid = threadIdx.x;
    int h = tid >> 5, i = tid & 31;
    __shared__ float sk[KK*CZ];
    __shared__ float sv[KK*CZ];
    for (int p = tid; p < KK*CZ; p += 128) {
        int jj = p >> 7, c = p & 127;
        size_t base = (size_t)(n*KK + jj) * 512;
        sk[p] = g_qkvo[base + 128 + c];
        sv[p] = g_qkvo[base + 256 + c];
    }
    float qr[32];
    const float scale = 0.17677669529663687f;   // 1/sqrt(32)
    size_t erow = (size_t)(n*KK + i) * 512;
    #pragma unroll
    for (int d = 0; d < 32; d++) qr[d] = g_qkvo[erow + h*32 + d] * scale;
    __syncthreads();

    float s[32];
    float mx = -1e30f;
    const float* bp = g_bias + (((size_t)n*NH + h)*KK + i)*KK;
    #pragma unroll
    for (int jj = 0; jj < 32; jj++) {
        float acc = bp[jj];
        const float* kp = sk + jj*128 + h*32;
        #pragma unroll
        for (int d = 0; d < 32; d++) acc += qr[d] * kp[d];
        s[jj] = acc;
        mx = fmaxf(mx, acc);
    }
    float sum = 0.f;
    #pragma unroll
    for (int jj = 0; jj < 32; jj++) { s[jj] = __expf(s[jj] - mx); sum += s[jj]; }
    float inv = __fdividef(1.f, sum);
    float* op = g_og + (size_t)(n*KK + i)*CZ + h*32;
    const float* ogp = g_qkvo + erow + 384 + h*32;
    #pragma unroll
    for (int d = 0; d < 32; d++) {
        float acc = 0.f;
        const float* vp = sv + h*32 + d;
        #pragma unroll
        for (int jj = 0; jj < 32; jj++) acc += s[jj] * vp[jj*128];
        op[d] = acc * inv * ogp[d];
    }
}

// ---------------- launch ----------------
extern "C" void kernel_launch(void* const* d_in, const int* in_sizes, int n_in,
                              void* d_out, int out_size)
{
    const float* nf       = (const float*)d_in[0];
    const float* trans    = (const float*)d_in[1];
    const float* ef       = (const float*)d_in[2];
    const int*   ei       = (const int*)d_in[3];
    const float* w_left   = (const float*)d_in[4];
    const float* b_left   = (const float*)d_in[5];
    const float* w_right  = (const float*)d_in[6];
    const float* b_right  = (const float*)d_in[7];
    const float* w_bgate  = (const float*)d_in[8];
    const float* b_bgate  = (const float*)d_in[9];
    const float* w_dist   = (const float*)d_in[10];
    const float* b_dist   = (const float*)d_in[11];
    const float* w_tobias = (const float*)d_in[12];
    const float* ln_g     = (const float*)d_in[13];
    const float* ln_b     = (const float*)d_in[14];
    const float* w_q      = (const float*)d_in[15];
    const float* b_q      = (const float*)d_in[16];
    const float* w_kv     = (const float*)d_in[17];
    const float* b_kv     = (const float*)d_in[18];
    const float* w_out    = (const float*)d_in[19];
    const float* b_out    = (const float*)d_in[20];
    const float* w_ogate  = (const float*)d_in[21];
    const float* b_ogate  = (const float*)d_in[22];
    float* out = (float*)d_out;

    float *p_z, *p_qkvo, *p_og, *p_wcat, *p_bcat;
    cudaGetSymbolAddress((void**)&p_z,    g_z);
    cudaGetSymbolAddress((void**)&p_qkvo, g_qkvo);
    cudaGetSymbolAddress((void**)&p_og,   g_og);
    cudaGetSymbolAddress((void**)&p_wcat, g_wcat);
    cudaGetSymbolAddress((void**)&p_bcat, g_bcat);

    k_concat<<<128, 512>>>(w_q, b_q, w_kv, b_kv, w_ogate, b_ogate);
    k_nlr<<<NN, 32>>>(nf, w_left, b_left, w_right, b_right);
    k_ln<<<EE, 128>>>(ef, ln_g, ln_b);
    // k_tri is launch #4 (ncu -s 5 -c 1 captures it)
    k_tri<<<NN, 1024>>>(ei, trans, w_bgate, b_bgate, w_dist, b_dist, w_tobias);
    {
        dim3 g(EE/128, 512/128);
        k_gemm_tc<<<g, 256>>>(p_z, p_wcat, p_qkvo, 512, p_bcat, 384);
    }
    k_attn<<<NN, 128>>>();
    {
        dim3 g(EE/128, 1);
        k_gemm_tc<<<g, 256>>>(p_og, w_out, out, 128, b_out, 1 << 30);
    }
}